// round 1
// baseline (speedup 1.0000x reference)
#include <cuda_runtime.h>

// Problem dims
#define R_  4
#define B_  512
#define T_  150
#define HD  32
#define K_  600      // R_*T_

// Intermediate attf buffer, laid out [b][r*T_ + t]  (== feats_final row-major)
__device__ float g_attf[B_ * K_];

// ---------------- helpers ----------------

__device__ __forceinline__ float tanha(float x) {
    float y;
    asm("tanh.approx.f32 %0, %1;" : "=f"(y) : "f"(x));
    return y;
}

__device__ __forceinline__ unsigned long long pk2(float lo, float hi) {
    unsigned long long r;
    asm("mov.b64 %0, {%1, %2};" : "=l"(r) : "f"(lo), "f"(hi));
    return r;
}

__device__ __forceinline__ void fma2(unsigned long long &acc,
                                     unsigned long long u,
                                     unsigned long long w) {
    asm("fma.rn.f32x2 %0, %1, %2, %0;" : "+l"(acc) : "l"(u), "l"(w));
}

__device__ __forceinline__ float2 up2(unsigned long long v) {
    float lo, hi;
    asm("mov.b64 {%0, %1}, %2;" : "=f"(lo), "=f"(hi) : "l"(v));
    return make_float2(lo, hi);
}

// ---------------- kernel A: att/Hm/attf ----------------
// grid (B_, R_), block 160 (150 active t lanes)
// dyn smem: wc[32*600] | g[600] | W[32] | Wh[32]
#define SMEM_A_FLOATS (HD*K_ + K_ + HD + HD)
#define SMEM_A_BYTES  (SMEM_A_FLOATS * sizeof(float))

__global__ __launch_bounds__(160, 2)
void camA(const float* __restrict__ feats,
          const float* __restrict__ a,
          const float* __restrict__ W,
          const float* __restrict__ Wc,
          const float* __restrict__ Wh)
{
    extern __shared__ float smem[];
    float* wc_s = smem;                  // [HD][K_] c-major (native Wc layout)
    float* g_s  = smem + HD * K_;        // [K_]
    float* W_s  = g_s + K_;              // [HD]
    float* Wh_s = W_s + HD;              // [HD]

    const int b   = blockIdx.x;
    const int r   = blockIdx.y;
    const int tid = threadIdx.x;

    // stage Wc[r] (coalesced float4 copy; layout identical to global)
    {
        const float4* src = (const float4*)(Wc + r * HD * K_);
        float4* dst = (float4*)wc_s;
        #pragma unroll
        for (int i = tid; i < HD * K_ / 4; i += 160) dst[i] = src[i];
    }
    // stage feat_n row b (raw reinterpretation: feat_n[b,k] = feats_flat[b*600+k])
    {
        const float4* src = (const float4*)(feats + b * K_);
        float4* dst = (float4*)g_s;
        for (int i = tid; i < K_ / 4; i += 160) dst[i] = src[i];
    }
    if (tid < HD) {
        W_s[tid]  = W[r * HD + tid];
        Wh_s[tid] = Wh[r * HD + tid];
    }

    const float ar = __ldg(a + r);
    float fv = 0.0f;
    if (tid < T_) fv = feats[(r * B_ + b) * T_ + tid];

    __syncthreads();

    const float x = ar * fv;

    unsigned long long acc[HD];
    #pragma unroll
    for (int c = 0; c < HD; c++) acc[c] = 0ull;   // (0.0f, 0.0f)

    #pragma unroll 1
    for (int k0 = 0; k0 < K_; k0 += 4) {
        float4 g4 = *(const float4*)(g_s + k0);
        float u0 = tanha(x * g4.x);
        float u1 = tanha(x * g4.y);
        float u2 = tanha(x * g4.z);
        float u3 = tanha(x * g4.w);
        unsigned long long u01 = pk2(u0, u1);
        unsigned long long u23 = pk2(u2, u3);
        #pragma unroll
        for (int c = 0; c < HD; c++) {
            float4 w4 = *(const float4*)(wc_s + c * K_ + k0);  // warp-broadcast
            fma2(acc[c], u01, pk2(w4.x, w4.y));
            fma2(acc[c], u23, pk2(w4.z, w4.w));
        }
    }

    if (tid < T_) {
        float attv = 0.0f;
        #pragma unroll
        for (int c = 0; c < HD; c++) {
            float2 s = up2(acc[c]);
            float hm = s.x + s.y + fv * W_s[c];
            hm = fmaxf(hm, 0.0f);
            attv = fmaf(hm, Wh_s[c], attv);
        }
        g_attf[b * K_ + r * T_ + tid] = attv + fv;
    }
}

// ---------------- kernel B: tiny MLP 600->128->7 ----------------
// grid 128, block 128; each block handles 4 batch rows (W1 re-read amortized 4x)
__global__ __launch_bounds__(128)
void camB(const float* __restrict__ W1,
          const float* __restrict__ b1,
          const float* __restrict__ W2,
          const float* __restrict__ b2,
          float* __restrict__ out)
{
    __shared__ __align__(16) float v_s[4][K_];
    __shared__ float h_s[4][128];

    const int bg   = blockIdx.x;      // group of 4 batches
    const int tid  = threadIdx.x;
    const int lane = tid & 31;
    const int w    = tid >> 5;

    // load 4 contiguous attf rows (4*600 floats, contiguous in g_attf)
    {
        const float4* src = (const float4*)(g_attf + bg * 4 * K_);
        float4* dst = (float4*)&v_s[0][0];
        for (int i = tid; i < 4 * K_ / 4; i += 128) dst[i] = src[i];
    }
    __syncthreads();

    // h = v @ W1^T + b1 : warp w handles c in [w*32, w*32+32)
    for (int cc = 0; cc < 32; cc++) {
        const int c = w * 32 + cc;
        float p0 = 0.f, p1 = 0.f, p2 = 0.f, p3 = 0.f;
        #pragma unroll
        for (int it = 0; it < 19; it++) {
            int k = it * 32 + lane;
            if (k < K_) {
                float w1 = W1[c * K_ + k];
                p0 = fmaf(w1, v_s[0][k], p0);
                p1 = fmaf(w1, v_s[1][k], p1);
                p2 = fmaf(w1, v_s[2][k], p2);
                p3 = fmaf(w1, v_s[3][k], p3);
            }
        }
        #pragma unroll
        for (int off = 16; off; off >>= 1) {
            p0 += __shfl_down_sync(0xffffffffu, p0, off);
            p1 += __shfl_down_sync(0xffffffffu, p1, off);
            p2 += __shfl_down_sync(0xffffffffu, p2, off);
            p3 += __shfl_down_sync(0xffffffffu, p3, off);
        }
        if (lane == 0) {
            float bb = b1[c];
            h_s[0][c] = p0 + bb;
            h_s[1][c] = p1 + bb;
            h_s[2][c] = p2 + bb;
            h_s[3][c] = p3 + bb;
        }
    }
    __syncthreads();

    // out = h @ W2^T + b2  (4 batches x 7 outputs = 28 dots of length 128)
    if (tid < 28) {
        const int j = tid / 7;   // local batch
        const int o = tid % 7;   // output idx
        float s = b2[o];
        #pragma unroll 8
        for (int c = 0; c < 128; c++)
            s = fmaf(W2[o * 128 + c], h_s[j][c], s);
        out[(bg * 4 + j) * 7 + o] = s;
    }
}

// ---------------- launch ----------------

extern "C" void kernel_launch(void* const* d_in, const int* in_sizes, int n_in,
                              void* d_out, int out_size)
{
    const float* feats = (const float*)d_in[0];  // (4,512,1,150)
    const float* a     = (const float*)d_in[1];  // (4,)
    const float* W     = (const float*)d_in[2];  // (4,32)
    const float* Wc    = (const float*)d_in[3];  // (4,32,600)
    const float* Wh    = (const float*)d_in[4];  // (4,32)
    const float* W1    = (const float*)d_in[5];  // (128,600)
    const float* b1    = (const float*)d_in[6];  // (128,)
    const float* W2    = (const float*)d_in[7];  // (7,128)
    const float* b2    = (const float*)d_in[8];  // (7,)
    float* out = (float*)d_out;                  // (512,1,7)

    cudaFuncSetAttribute(camA, cudaFuncAttributeMaxDynamicSharedMemorySize,
                         (int)SMEM_A_BYTES);

    dim3 gridA(B_, R_);
    camA<<<gridA, 160, SMEM_A_BYTES>>>(feats, a, W, Wc, Wh);
    camB<<<128, 128>>>(W1, b1, W2, b2, out);
}

// round 3
// speedup vs baseline: 3.9411x; 3.9411x over previous
#include <cuda_runtime.h>
#include <cuda_bf16.h>
#include <cstdint>

#define R_   4
#define B_   512
#define T_   150
#define HD   32
#define K_   600
#define KPAD 608          // 38 k16 steps
#define KS   616          // smem/storage row stride (elems): 308 words == 20 mod 32 -> conflict-free
#define NSTEP 38

// device intermediates (no allocs allowed)
__device__ float g_attf[B_ * K_];
__device__ __nv_bfloat16 g_wcb[R_ * HD * KS];   // bf16 Wc, padded rows
__device__ float g_w1t[K_ * 128];               // W1 transposed [k][c]

// ---------------- helpers ----------------
__device__ __forceinline__ float tanha(float x) {
    float y; asm("tanh.approx.f32 %0, %1;" : "=f"(y) : "f"(x)); return y;
}
// pack (lo,hi) -> bf16x2 (lo in low half)
__device__ __forceinline__ uint32_t packbf(float lo, float hi) {
    uint32_t r; asm("cvt.rn.satfinite.bf16x2.f32 %0, %1, %2;" : "=r"(r) : "f"(hi), "f"(lo)); return r;
}
__device__ __forceinline__ void mma16816(float* d,
    uint32_t a0, uint32_t a1, uint32_t a2, uint32_t a3,
    uint32_t b0, uint32_t b1)
{
    asm volatile(
        "mma.sync.aligned.m16n8k16.row.col.f32.bf16.bf16.f32 "
        "{%0,%1,%2,%3}, {%4,%5,%6,%7}, {%8,%9}, {%0,%1,%2,%3};"
        : "+f"(d[0]), "+f"(d[1]), "+f"(d[2]), "+f"(d[3])
        : "r"(a0), "r"(a1), "r"(a2), "r"(a3), "r"(b0), "r"(b1));
}

// ---------------- prep: Wc->bf16 padded + W1 transpose ----------------
__global__ __launch_bounds__(256)
void camPrep(const float* __restrict__ Wc, const float* __restrict__ W1)
{
    int bid = blockIdx.x;
    if (bid < 308) {                         // Wc: 4*32*616 = 78848 elems
        int idx = bid * 256 + threadIdx.x;
        if (idx >= R_ * HD * KS) return;
        int rc = idx / KS;                   // r*32 + c
        int k  = idx - rc * KS;
        float v = (k < K_) ? Wc[rc * K_ + k] : 0.0f;
        g_wcb[idx] = __float2bfloat16(v);
    } else {                                 // W1T: 600*128 = 76800
        int idx = (bid - 308) * 256 + threadIdx.x;
        if (idx >= K_ * 128) return;
        int k = idx >> 7;
        int c = idx & 127;
        g_w1t[idx] = W1[c * K_ + k];
    }
}

// ---------------- kernel A ----------------
// grid (600, 4), block 256 (8 warps x 16 rows = 128 rows per CTA)
// smem: wc bf16[32][616] | g f32[2][616] | W[32] | Wh[32]
#define SM_WC  0
#define SM_G   (HD * KS * 2)                     // 39424
#define SM_W   (SM_G + 2 * KS * 4)               // 44352
#define SM_WH  (SM_W + 128)
#define SM_TOT (SM_WH + 128)                     // 44608 bytes

__global__ __launch_bounds__(256)
void camA(const float* __restrict__ feats,
          const float* __restrict__ a,
          const float* __restrict__ W,
          const float* __restrict__ Wh)
{
    extern __shared__ char smem[];
    __nv_bfloat16* wc_s = (__nv_bfloat16*)(smem + SM_WC);
    float*         g_s  = (float*)(smem + SM_G);
    float*         W_s  = (float*)(smem + SM_W);
    float*         Wh_s = (float*)(smem + SM_WH);

    const int tid = threadIdx.x;
    const int r   = blockIdx.y;
    const int m0  = blockIdx.x * 128;
    const int b0  = m0 / T_;

    // stage Wc[r] (linear uint4 copy of pre-padded bf16)
    {
        const uint4* src = (const uint4*)(g_wcb + r * HD * KS);
        uint4* dst = (uint4*)wc_s;
        #pragma unroll
        for (int i = tid; i < HD * KS * 2 / 16; i += 256) dst[i] = src[i];
    }
    // stage g rows b0, b0+1 (feat_n[b][k] == flat feats[b*600+k]); zero-pad
    for (int j = tid; j < 2 * KS; j += 256) {
        int jb = j / KS;
        int k  = j - jb * KS;
        float v = 0.0f;
        if (k < K_ && (b0 + jb) < B_) v = feats[(b0 + jb) * K_ + k];
        g_s[j] = v;
    }
    if (tid < HD) { W_s[tid] = W[r * HD + tid]; Wh_s[tid] = Wh[r * HD + tid]; }
    __syncthreads();

    const int w    = tid >> 5;
    const int lane = tid & 31;
    const int qid  = lane >> 2;      // 0..7
    const int qk   = lane & 3;       // 0..3

    const int row0 = m0 + w * 16 + qid;
    const int row1 = row0 + 8;
    const int bb0  = row0 / T_, tt0 = row0 - bb0 * T_;
    const int bb1  = row1 / T_, tt1 = row1 - bb1 * T_;

    const float ar = __ldg(a + r);
    const float f0 = __ldg(feats + (r * B_ + bb0) * T_ + tt0);
    const float f1 = __ldg(feats + (r * B_ + bb1) * T_ + tt1);
    const float x0 = ar * f0;
    const float x1 = ar * f1;

    const float* gp0 = g_s + (bb0 - b0) * KS + qk * 2;
    const float* gp1 = g_s + (bb1 - b0) * KS + qk * 2;
    const __nv_bfloat16* wcp = wc_s + qid * KS + qk * 2;

    float d[4][4];
    #pragma unroll
    for (int g = 0; g < 4; g++)
        #pragma unroll
        for (int i = 0; i < 4; i++) d[g][i] = 0.0f;

    #pragma unroll 2
    for (int s = 0; s < NSTEP; s++) {
        const int k0 = s * 16;
        float2 gA0 = *(const float2*)(gp0 + k0);
        float2 gA8 = *(const float2*)(gp0 + k0 + 8);
        float2 gB0 = *(const float2*)(gp1 + k0);
        float2 gB8 = *(const float2*)(gp1 + k0 + 8);
        uint32_t a0 = packbf(tanha(x0 * gA0.x), tanha(x0 * gA0.y));
        uint32_t a1 = packbf(tanha(x1 * gB0.x), tanha(x1 * gB0.y));
        uint32_t a2 = packbf(tanha(x0 * gA8.x), tanha(x0 * gA8.y));
        uint32_t a3 = packbf(tanha(x1 * gB8.x), tanha(x1 * gB8.y));
        #pragma unroll
        for (int g = 0; g < 4; g++) {
            const __nv_bfloat16* bp = wcp + g * 8 * KS + k0;
            uint32_t bf0 = *(const uint32_t*)(bp);
            uint32_t bf1 = *(const uint32_t*)(bp + 8);
            mma16816(d[g], a0, a1, a2, a3, bf0, bf1);
        }
    }

    // epilogue: relu(D + f*W)*Wh, reduce over c (8 per thread, x4 threads in quad)
    float p0 = 0.0f, p1 = 0.0f;
    #pragma unroll
    for (int g = 0; g < 4; g++) {
        float2 Wp  = *(const float2*)(W_s  + g * 8 + qk * 2);
        float2 Whp = *(const float2*)(Wh_s + g * 8 + qk * 2);
        p0 += fmaxf(fmaf(f0, Wp.x, d[g][0]), 0.0f) * Whp.x
            + fmaxf(fmaf(f0, Wp.y, d[g][1]), 0.0f) * Whp.y;
        p1 += fmaxf(fmaf(f1, Wp.x, d[g][2]), 0.0f) * Whp.x
            + fmaxf(fmaf(f1, Wp.y, d[g][3]), 0.0f) * Whp.y;
    }
    p0 += __shfl_xor_sync(0xffffffffu, p0, 1);
    p0 += __shfl_xor_sync(0xffffffffu, p0, 2);
    p1 += __shfl_xor_sync(0xffffffffu, p1, 1);
    p1 += __shfl_xor_sync(0xffffffffu, p1, 2);

    if (qk == 0) {
        g_attf[bb0 * K_ + r * T_ + tt0] = p0 + f0;
        g_attf[bb1 * K_ + r * T_ + tt1] = p1 + f1;
    }
}

// ---------------- kernel B: MLP 600->128->7, 8 batches per CTA ----------------
__global__ __launch_bounds__(128)
void camB(const float* __restrict__ b1,
          const float* __restrict__ W2,
          const float* __restrict__ b2,
          float* __restrict__ out)
{
    __shared__ __align__(16) float v_s[8 * K_];
    __shared__ float h_s[8 * 128];

    const int bg  = blockIdx.x;       // batch group of 8
    const int tid = threadIdx.x;

    // stage 8 contiguous attf rows (linear)
    {
        const float4* src = (const float4*)(g_attf + bg * 8 * K_);
        float4* dst = (float4*)v_s;
        #pragma unroll
        for (int i = tid; i < 8 * K_ / 4; i += 128) dst[i] = src[i];
    }
    __syncthreads();

    // h[j][c] for c = tid
    {
        float acc[8];
        #pragma unroll
        for (int j = 0; j < 8; j++) acc[j] = 0.0f;
        #pragma unroll 4
        for (int k = 0; k < K_; k++) {
            float w1 = __ldg(g_w1t + k * 128 + tid);
            #pragma unroll
            for (int j = 0; j < 8; j++)
                acc[j] = fmaf(w1, v_s[j * K_ + k], acc[j]);
        }
        float bb = __ldg(b1 + tid);
        #pragma unroll
        for (int j = 0; j < 8; j++) h_s[j * 128 + tid] = acc[j] + bb;
    }
    __syncthreads();

    // out[j][o] = h[j] . W2[o] + b2[o]
    if (tid < 56) {
        const int j = tid / 7;
        const int o = tid - j * 7;
        float s = __ldg(b2 + o);
        const float* hp = h_s + j * 128;
        const float* wp = W2 + o * 128;
        #pragma unroll 8
        for (int c = 0; c < 128; c++)
            s = fmaf(__ldg(wp + c), hp[c], s);
        out[(bg * 8 + j) * 7 + o] = s;
    }
}

// ---------------- launch ----------------
extern "C" void kernel_launch(void* const* d_in, const int* in_sizes, int n_in,
                              void* d_out, int out_size)
{
    const float* feats = (const float*)d_in[0];
    const float* a     = (const float*)d_in[1];
    const float* W     = (const float*)d_in[2];
    const float* Wc    = (const float*)d_in[3];
    const float* Wh    = (const float*)d_in[4];
    const float* W1    = (const float*)d_in[5];
    const float* b1    = (const float*)d_in[6];
    const float* W2    = (const float*)d_in[7];
    const float* b2    = (const float*)d_in[8];
    float* out = (float*)d_out;

    cudaFuncSetAttribute(camA, cudaFuncAttributeMaxDynamicSharedMemorySize, SM_TOT);

    camPrep<<<608, 256>>>(Wc, W1);
    dim3 gridA(600, R_);
    camA<<<gridA, 256, SM_TOT>>>(feats, a, W, Wh);
    camB<<<B_ / 8, 128>>>(b1, W2, b2, out);
}